// round 6
// baseline (speedup 1.0000x reference)
#include <cuda_runtime.h>
#include <cuda_bf16.h>
#include <cstdint>
#include <cstddef>

#define B_ 4
#define V_ 64
#define E_ 1024
#define L_ 1024
#define D_ 256
#define BE_ (B_*E_)
#define SLOTS 16
#define MAXE 32

// ---------------- device scratch ----------------
// Mt split images, k-slice-major: [slice s(16)][j(256)][dk(16)] bf16, 8KB/slice
__device__ __align__(16) unsigned char g_Bhi[16*8192];
__device__ __align__(16) unsigned char g_Blo[16*8192];
__device__ __align__(16) float g_u[D_];
__device__ __align__(16) float g_t[D_];
__device__ float g_c;
__device__ int   g_ndeg[V_];
__device__ int   g_ecnt[V_];
__device__ int   g_ndst[V_*SLOTS];
__device__ int   g_vedge[V_*MAXE];   // e | (slot<<16)
__device__ int   g_eslot[E_];
__device__ float g_adjw[B_*V_*SLOTS];

// ---------------- helpers ----------------
__device__ __forceinline__ uint32_t smem_u32(const void* p) {
    uint32_t a;
    asm("{ .reg .u64 t; cvta.to.shared.u64 t, %1; cvt.u32.u64 %0, t; }" : "=r"(a) : "l"(p));
    return a;
}
__device__ __forceinline__ void ldsm4(uint32_t* r, uint32_t addr) {
    asm volatile("ldmatrix.sync.aligned.m8n8.x4.shared.b16 {%0,%1,%2,%3}, [%4];"
        : "=r"(r[0]), "=r"(r[1]), "=r"(r[2]), "=r"(r[3]) : "r"(addr));
}
__device__ __forceinline__ void mma16816(float* d, const uint32_t* a, uint32_t b0, uint32_t b1) {
    asm volatile("mma.sync.aligned.m16n8k16.row.col.f32.bf16.bf16.f32 "
        "{%0,%1,%2,%3}, {%4,%5,%6,%7}, {%8,%9}, {%0,%1,%2,%3};"
        : "+f"(d[0]), "+f"(d[1]), "+f"(d[2]), "+f"(d[3])
        : "r"(a[0]), "r"(a[1]), "r"(a[2]), "r"(a[3]), "r"(b0), "r"(b1));
}
__device__ __forceinline__ uint32_t pack_bf2(float a, float b) {
    __nv_bfloat162 t = __floats2bfloat162_rn(a, b);
    return *reinterpret_cast<uint32_t*>(&t);
}

// A/T row stride: 264 bf16 = 528B (8 rows cover distinct 16B lanes mod 128B)
#define ASTR 528
// B slice row stride: 48B (32B data + 16B pad)
#define BSTR 48

// smem byte offsets
#define SM_AHI  0
#define SM_ALO  33792
#define SM_THI  67584
#define SM_TLO  101376
#define SM_B    135168        // hi0, hi1, lo0, lo1 each 12288
#define SM_S    184320        // 64 x 68 fp32
#define MS_DST  201728
#define MS_ADJ  205824
#define MS_VED  209920
#define MS_DEG  218112
#define MS_ECNT 218368
#define MS_P    218624
#define MS_R    218880
#define MS_PP   219136
#define MS_RP   221184
#define SMEM_BYTES 223232

// ---------------- K0: Mt split images + u, t, c ----------------
__global__ void k0_prep(const float* __restrict__ Wq, const float* __restrict__ bq,
                        const float* __restrict__ Wk, const float* __restrict__ bk) {
    __shared__ float swk[D_];
    const int j = blockIdx.x, d = threadIdx.x;
    swk[d] = Wk[d*D_ + j];
    __syncthreads();
    float acc = 0.f;
#pragma unroll 8
    for (int k = 0; k < D_; ++k) acc += Wq[k*D_ + d] * swk[k];
    {   // Mt[j][d] = M[d][j]
        __nv_bfloat16 hi = __float2bfloat16(acc);
        __nv_bfloat16 lo = __float2bfloat16(acc - __bfloat162float(hi));
        const int s = d >> 4, dk = d & 15;
        const uint32_t off = (uint32_t)s*8192u + (uint32_t)j*32u + (uint32_t)dk*2u;
        *reinterpret_cast<__nv_bfloat16*>(g_Bhi + off) = hi;
        *reinterpret_cast<__nv_bfloat16*>(g_Blo + off) = lo;
    }
    if (d == 0) {
        float s = 0.f;
        for (int k = 0; k < D_; ++k) s += bq[k] * swk[k];
        g_t[j] = s;
    }
    if (j == 0) {
        float s = 0.f;
        for (int k = 0; k < D_; ++k) s += Wq[k*D_ + d] * bk[k];
        g_u[d] = s;
    }
    if (j == 0 && d == 0) {
        float s = 0.f;
        for (int k = 0; k < D_; ++k) s += bq[k] * bk[k];
        g_c = s;
    }
}

// ---------------- K1 / K1b: graph metadata (verified) ----------------
__global__ void k1_build(const int* __restrict__ ei) {
    const int v = threadIdx.x;
    int deg = 0, ecnt = 0;
    for (int e = 0; e < E_; ++e) {
        int s = ei[e];
        if (s == v) {
            int dd = ei[BE_ + e];
            int slot = -1;
            for (int k = 0; k < deg; ++k)
                if (g_ndst[v*SLOTS + k] == dd) { slot = k; break; }
            if (slot < 0 && deg < SLOTS) { slot = deg; g_ndst[v*SLOTS + deg] = dd; ++deg; }
            if (slot >= 0) {
                g_eslot[e] = slot;
                if (ecnt < MAXE) g_vedge[v*MAXE + ecnt++] = e | (slot << 16);
            }
        }
    }
    g_ndeg[v] = deg;
    g_ecnt[v] = ecnt;
    for (int b = 0; b < B_; ++b)
        for (int k = 0; k < SLOTS; ++k)
            g_adjw[(b*V_ + v)*SLOTS + k] = 0.f;
}

__global__ void k1b_adjw(const int* __restrict__ ei, const float* __restrict__ ew) {
    const int i = blockIdx.x * blockDim.x + threadIdx.x;
    if (i >= BE_) return;
    const int e = i & (E_ - 1);
    const int b = i >> 10;
    const int v = ei[i];
    const int slot = g_eslot[e];
    atomicAdd(&g_adjw[(b*V_ + v)*SLOTS + slot], ew[i]);
}

// ---------------- K2: fused per-(b,l) attention on HMMA ----------------
__global__ void __launch_bounds__(512, 1) k2_main(
    const float* __restrict__ hs, const float* __restrict__ attn_skip,
    float* __restrict__ ew_out) {
    extern __shared__ __align__(16) unsigned char sm[];
    const uint32_t sb = smem_u32(sm);
    const int tid = threadIdx.x;
    const int lane = tid & 31, warp = tid >> 5;
    const int b = blockIdx.x >> 10;
    const int l = blockIdx.x & 1023;

    int*   sDst  = (int*)(sm + MS_DST);
    float* sAdj  = (float*)(sm + MS_ADJ);
    int*   sVed  = (int*)(sm + MS_VED);
    int*   sDeg  = (int*)(sm + MS_DEG);
    int*   sEcnt = (int*)(sm + MS_ECNT);
    float* sP    = (float*)(sm + MS_P);
    float* sR    = (float*)(sm + MS_R);
    float* sPp   = (float*)(sm + MS_PP);
    float* sRp   = (float*)(sm + MS_RP);
    float* sS    = (float*)(sm + SM_S);   // [64][68]

    // metadata
    if (tid < 64) { sDeg[tid] = g_ndeg[tid]; sEcnt[tid] = g_ecnt[tid]; }
    for (int i = tid; i < 64*SLOTS; i += 512) {
        sDst[i] = g_ndst[i];
        sAdj[i] = g_adjw[b*64*SLOTS + i];
    }
    for (int i = tid; i < 64*MAXE; i += 512) sVed[i] = g_vedge[i];

    // H load + bf16 split + bias partials: thread -> (v = tid>>3, part = tid&7)
    {
        const int v = tid >> 3, part = tid & 7;
        const float4* hrow = (const float4*)(hs
            + (((size_t)(b*64 + v))*1024 + l)*256) + part*8;
        const float4* u4 = (const float4*)g_u + part*8;
        const float4* t4 = (const float4*)g_t + part*8;
        float pp = 0.f, rr = 0.f;
#pragma unroll
        for (int i = 0; i < 8; ++i) {
            float4 f = hrow[i];
            float4 uu = u4[i], tt = t4[i];
            pp += f.x*uu.x + f.y*uu.y + f.z*uu.z + f.w*uu.w;
            rr += f.x*tt.x + f.y*tt.y + f.z*tt.z + f.w*tt.w;
            __nv_bfloat16 h0 = __float2bfloat16(f.x), h1 = __float2bfloat16(f.y);
            __nv_bfloat16 h2 = __float2bfloat16(f.z), h3 = __float2bfloat16(f.w);
            uint32_t hi01, hi23, lo01, lo23;
            { __nv_bfloat162 t2 = make_bfloat162(h0, h1); hi01 = *(uint32_t*)&t2; }
            { __nv_bfloat162 t2 = make_bfloat162(h2, h3); hi23 = *(uint32_t*)&t2; }
            lo01 = pack_bf2(f.x - __bfloat162float(h0), f.y - __bfloat162float(h1));
            lo23 = pack_bf2(f.z - __bfloat162float(h2), f.w - __bfloat162float(h3));
            const uint32_t off = (uint32_t)v*ASTR + (uint32_t)(part*32 + i*4)*2;
            *(uint2*)(sm + SM_AHI + off) = make_uint2(hi01, hi23);
            *(uint2*)(sm + SM_ALO + off) = make_uint2(lo01, lo23);
        }
        sPp[tid] = pp; sRp[tid] = rr;
    }

    // stage B slice 0
    uint4 stH = *(const uint4*)(g_Bhi + tid*16);
    uint4 stL = *(const uint4*)(g_Blo + tid*16);
    __syncthreads();

    // bias reduction
    if (tid < 64) {
        float p = 0.f, r = 0.f;
#pragma unroll
        for (int i = 0; i < 8; ++i) { p += sPp[tid*8 + i]; r += sRp[tid*8 + i]; }
        sP[tid] = p; sR[tid] = r;
    }

    // ---- GEMM1: T(64x256) = Hsplit @ Mtsplit, 16 k-slices ----
    const int mg = warp >> 3;          // 0..1  (32 rows)
    const int ng = warp & 7;           // 0..7  (32 cols)
    const int arow = (lane & 15);
    const int akoff = (lane >> 4) * 8;
    const int bjoff = ((lane >> 4) << 3) + (lane & 7);
    const int bdk = ((lane >> 3) & 1) * 8;
    const int brow_half = tid >> 1, bhalf = tid & 1;

    float acc[2][4][4];
#pragma unroll
    for (int mt = 0; mt < 2; ++mt)
#pragma unroll
        for (int n8 = 0; n8 < 4; ++n8)
#pragma unroll
            for (int i = 0; i < 4; ++i) acc[mt][n8][i] = 0.f;

    for (int s = 0; s < 16; ++s) {
        // STS staged slice s into buf[s&1]
        {
            const uint32_t o = (uint32_t)(s & 1)*12288u + (uint32_t)brow_half*BSTR + (uint32_t)bhalf*16u;
            *(uint4*)(sm + SM_B + o)          = stH;
            *(uint4*)(sm + SM_B + 24576 + o)  = stL;
        }
        if (s < 15) {
            stH = *(const uint4*)(g_Bhi + (s+1)*8192 + tid*16);
            stL = *(const uint4*)(g_Blo + (s+1)*8192 + tid*16);
        }
        __syncthreads();

        uint32_t aHi[2][4], aLo[2][4], bHi[2][4], bLo[2][4];
#pragma unroll
        for (int mt = 0; mt < 2; ++mt) {
            const uint32_t ao = (uint32_t)(mg*32 + mt*16 + arow)*ASTR + (uint32_t)(s*16 + akoff)*2;
            ldsm4(aHi[mt], sb + SM_AHI + ao);
            ldsm4(aLo[mt], sb + SM_ALO + ao);
        }
#pragma unroll
        for (int grp = 0; grp < 2; ++grp) {
            const uint32_t bo = (uint32_t)(s & 1)*12288u
                              + (uint32_t)(ng*32 + grp*16 + bjoff)*BSTR + (uint32_t)bdk*2;
            ldsm4(bHi[grp], sb + SM_B + bo);
            ldsm4(bLo[grp], sb + SM_B + 24576 + bo);
        }
#pragma unroll
        for (int mt = 0; mt < 2; ++mt)
#pragma unroll
            for (int grp = 0; grp < 2; ++grp)
#pragma unroll
                for (int q = 0; q < 2; ++q) {
                    const int n8 = grp*2 + q;
                    mma16816(acc[mt][n8], aHi[mt], bHi[grp][2*q], bHi[grp][2*q+1]);
                    mma16816(acc[mt][n8], aHi[mt], bLo[grp][2*q], bLo[grp][2*q+1]);
                    mma16816(acc[mt][n8], aLo[mt], bHi[grp][2*q], bHi[grp][2*q+1]);
                }
    }

    // ---- T -> bf16 split into sThi/sTlo ----
    {
        const int g = lane >> 2, t2 = lane & 3;
#pragma unroll
        for (int mt = 0; mt < 2; ++mt)
#pragma unroll
            for (int n8 = 0; n8 < 4; ++n8) {
                const int col = ng*32 + n8*8 + t2*2;
                const int r0 = mg*32 + mt*16 + g;
#pragma unroll
                for (int half = 0; half < 2; ++half) {
                    const float c0 = acc[mt][n8][half*2], c1 = acc[mt][n8][half*2 + 1];
                    const int row = r0 + half*8;
                    __nv_bfloat16 h0 = __float2bfloat16(c0), h1 = __float2bfloat16(c1);
                    __nv_bfloat162 hp = make_bfloat162(h0, h1);
                    const uint32_t hv = *(uint32_t*)&hp;
                    const uint32_t lv = pack_bf2(c0 - __bfloat162float(h0), c1 - __bfloat162float(h1));
                    const uint32_t off = (uint32_t)row*ASTR + (uint32_t)col*2;
                    *(uint32_t*)(sm + SM_THI + off) = hv;
                    *(uint32_t*)(sm + SM_TLO + off) = lv;
                }
            }
    }
    __syncthreads();

    // ---- GEMM2: S(64x64) = Tsplit @ Hsplit^T ----
    {
        const int mg2 = warp >> 2;      // 0..3 (16 rows)
        const int ng2 = warp & 3;       // 0..3 (16 cols)
        float acc2[2][4];
#pragma unroll
        for (int q = 0; q < 2; ++q)
#pragma unroll
            for (int i = 0; i < 4; ++i) acc2[q][i] = 0.f;

        for (int s = 0; s < 16; ++s) {
            uint32_t aHi[4], aLo[4], bHi[4], bLo[4];
            const uint32_t ao = (uint32_t)(mg2*16 + arow)*ASTR + (uint32_t)(s*16 + akoff)*2;
            ldsm4(aHi, sb + SM_THI + ao);
            ldsm4(aLo, sb + SM_TLO + ao);
            const uint32_t bo = (uint32_t)(ng2*16 + bjoff)*ASTR + (uint32_t)(s*16 + bdk)*2;
            ldsm4(bHi, sb + SM_AHI + bo);
            ldsm4(bLo, sb + SM_ALO + bo);
#pragma unroll
            for (int q = 0; q < 2; ++q) {
                mma16816(acc2[q], aHi, bHi[2*q], bHi[2*q+1]);
                mma16816(acc2[q], aHi, bLo[2*q], bLo[2*q+1]);
                mma16816(acc2[q], aLo, bHi[2*q], bHi[2*q+1]);
            }
        }
        // write S fp32
        const int g = lane >> 2, t2 = lane & 3;
#pragma unroll
        for (int q = 0; q < 2; ++q) {
            const int col = ng2*16 + q*8 + t2*2;
            *(float2*)&sS[(mg2*16 + g)*68 + col]     = make_float2(acc2[q][0], acc2[q][1]);
            *(float2*)&sS[(mg2*16 + g + 8)*68 + col] = make_float2(acc2[q][2], acc2[q][3]);
        }
    }
    __syncthreads();

    // ---- softmax over neighbor slots + per-edge output ----
    if (tid < 64) {
        const int v = tid, deg = sDeg[v];
        const float pv = sP[v], cC = g_c;
        float sc[SLOTS];
        float mx = -1e30f;
        for (int k = 0; k < deg; ++k) {
            const int w = sDst[v*SLOTS + k];
            const float s = (sS[v*68 + w] + pv + sR[w] + cC) * 0.0625f;
            sc[k] = s;
            mx = fmaxf(mx, s);
        }
        float sum = 0.f;
        for (int k = 0; k < deg; ++k) {
            const float e = __expf(sc[k] - mx);
            sc[k] = e;
            sum += e;
        }
        const float inv = 1.f / sum;
        const float ask = *attn_skip, osk = 1.f - ask;
        const int ecnt = sEcnt[v];
        for (int j = 0; j < ecnt; ++j) {
            const int w = sVed[v*MAXE + j];
            const int e = w & 0xFFFF, slot = w >> 16;
            const float gval = ask * sAdj[v*SLOTS + slot] + osk * (sc[slot] * inv);
            ew_out[((size_t)(b*E_ + e))*L_ + l] = gval;
        }
    }
}

// ---------------- K3: ei broadcast output ----------------
__global__ void k3_ei(const int* __restrict__ ei, float* __restrict__ out) {
    const size_t i = (size_t)blockIdx.x * blockDim.x + threadIdx.x;
    const size_t n = (size_t)2 * BE_ * L_;
    if (i < n) out[i] = (float)ei[i >> 10];
}

// ---------------- launch ----------------
extern "C" void kernel_launch(void* const* d_in, const int* in_sizes, int n_in,
                              void* d_out, int out_size) {
    const float* hs  = (const float*)d_in[0];
    const int*   ei  = (const int*)d_in[1];
    const float* ew  = (const float*)d_in[2];
    const float* Wq  = (const float*)d_in[3];
    const float* bq  = (const float*)d_in[4];
    const float* Wk  = (const float*)d_in[5];
    const float* bk  = (const float*)d_in[6];
    const float* ask = (const float*)d_in[7];

    float* out = (float*)d_out;
    const int EW_ELEMS = BE_ * L_;
    const int EI_ELEMS = 2 * BE_ * L_;
    float* ew_out = out;
    bool write_ei = false;
    if (out_size >= EI_ELEMS + EW_ELEMS) {
        write_ei = true;
        ew_out = out + EI_ELEMS;
    }

    cudaFuncSetAttribute(k2_main, cudaFuncAttributeMaxDynamicSharedMemorySize, SMEM_BYTES);

    k0_prep<<<D_, D_>>>(Wq, bq, Wk, bk);
    k1_build<<<1, V_>>>(ei);
    k1b_adjw<<<(BE_ + 255)/256, 256>>>(ei, ew);
    k2_main<<<B_*L_, 512, SMEM_BYTES>>>(hs, ask, ew_out);
    if (write_ei) k3_ei<<<(EI_ELEMS + 255)/256, 256>>>(ei, out);
}

// round 9
// speedup vs baseline: 1.6920x; 1.6920x over previous
#include <cuda_runtime.h>
#include <cuda_bf16.h>
#include <cstdint>
#include <cstddef>

#define B_ 4
#define V_ 64
#define E_ 1024
#define L_ 1024
#define D_ 256
#define BE_ (B_*E_)
#define SLOTS 16
#define MAXE 16

// ---------------- device scratch ----------------
// Fragment-ordered Mt images for direct per-warp LDG:
// uint4 index: ((ng*2+grp)*16 + s)*32 + lane   (ng 0..7, grp 0..1, s 0..15)
__device__ __align__(16) unsigned char g_BfH[8*2*16*32*16];   // 128KB
__device__ __align__(16) unsigned char g_BfL[8*2*16*32*16];   // 128KB
__device__ __align__(16) float g_u[D_];
__device__ __align__(16) float g_t[D_];
__device__ float g_c;
__device__ int   g_ndeg[V_];
__device__ int   g_ecnt[V_];
__device__ int   g_ndst[V_*SLOTS];
__device__ int   g_vedge[V_*MAXE];   // e | (slot<<16)
__device__ int   g_eslot[E_];
__device__ float g_adjw[B_*V_*SLOTS];

// ---------------- helpers ----------------
__device__ __forceinline__ uint32_t smem_u32(const void* p) {
    uint32_t a;
    asm("{ .reg .u64 t; cvta.to.shared.u64 t, %1; cvt.u32.u64 %0, t; }" : "=r"(a) : "l"(p));
    return a;
}
__device__ __forceinline__ void ldsm4(uint32_t* r, uint32_t addr) {
    asm volatile("ldmatrix.sync.aligned.m8n8.x4.shared.b16 {%0,%1,%2,%3}, [%4];"
        : "=r"(r[0]), "=r"(r[1]), "=r"(r[2]), "=r"(r[3]) : "r"(addr));
}
__device__ __forceinline__ void mma16816(float* d, const uint32_t* a, uint32_t b0, uint32_t b1) {
    asm volatile("mma.sync.aligned.m16n8k16.row.col.f32.bf16.bf16.f32 "
        "{%0,%1,%2,%3}, {%4,%5,%6,%7}, {%8,%9}, {%0,%1,%2,%3};"
        : "+f"(d[0]), "+f"(d[1]), "+f"(d[2]), "+f"(d[3])
        : "r"(a[0]), "r"(a[1]), "r"(a[2]), "r"(a[3]), "r"(b0), "r"(b1));
}
__device__ __forceinline__ uint32_t pack_bf2(float a, float b) {
    __nv_bfloat162 t = __floats2bfloat162_rn(a, b);
    return *reinterpret_cast<uint32_t*>(&t);
}

// A/T row stride: 264 bf16 = 528B
#define ASTR 528

// smem byte offsets
#define SM_AHI  0
#define SM_ALO  33792
#define SM_THI  67584
#define SM_TLO  101376
#define SM_S    135168        // 64 x 68 fp32 = 17408
#define MS_DST  152576
#define MS_ADJ  156672
#define MS_VED  160768
#define MS_DEG  164864
#define MS_ECNT 165120
#define MS_P    165376
#define MS_R    165632
#define MS_PP   165888
#define MS_RP   167936
#define MS_MX   169984
#define MS_INV  170240
#define SMEM_BYTES 170496

// ---------------- K0: fragment images + u, t, c ----------------
__global__ void k0_prep(const float* __restrict__ Wq, const float* __restrict__ bq,
                        const float* __restrict__ Wk, const float* __restrict__ bk) {
    __shared__ float swk[D_];
    const int j = blockIdx.x, d = threadIdx.x;
    swk[d] = Wk[d*D_ + j];
    __syncthreads();
    float acc = 0.f;
#pragma unroll 8
    for (int k = 0; k < D_; ++k) acc += Wq[k*D_ + d] * swk[k];
    {   // B[k=d][n=j] = M[d][j]; scatter into mma B-fragment order
        __nv_bfloat16 hi = __float2bfloat16(acc);
        __nv_bfloat16 lo = __float2bfloat16(acc - __bfloat162float(hi));
        const int s = d >> 4, dk = d & 15;
        const int r = dk >> 3, k2 = (dk >> 1) & 3, half = dk & 1;
        const int ng = j >> 5, grp = (j >> 4) & 1, n8l = (j >> 3) & 1;
        const int lane = (j & 7)*4 + k2;
        const int w = n8l*2 + r;
        const uint32_t word = ((((uint32_t)(ng*2 + grp))*16 + s)*32 + lane)*4 + w;
        const uint32_t byte = word*4 + half*2;
        *reinterpret_cast<__nv_bfloat16*>(g_BfH + byte) = hi;
        *reinterpret_cast<__nv_bfloat16*>(g_BfL + byte) = lo;
    }
    if (d == 0) {
        float s = 0.f;
        for (int k = 0; k < D_; ++k) s += bq[k] * swk[k];
        g_t[j] = s;
    }
    if (j == 0) {
        float s = 0.f;
        for (int k = 0; k < D_; ++k) s += Wq[k*D_ + d] * bk[k];
        g_u[d] = s;
    }
    if (j == 0 && d == 0) {
        float s = 0.f;
        for (int k = 0; k < D_; ++k) s += bq[k] * bk[k];
        g_c = s;
    }
}

// ---------------- K1 / K1b: graph metadata ----------------
__global__ void k1_build(const int* __restrict__ ei) {
    const int v = threadIdx.x;
    int deg = 0, ecnt = 0;
    for (int e = 0; e < E_; ++e) {
        int s = ei[e];
        if (s == v) {
            int dd = ei[BE_ + e];
            int slot = -1;
            for (int k = 0; k < deg; ++k)
                if (g_ndst[v*SLOTS + k] == dd) { slot = k; break; }
            if (slot < 0 && deg < SLOTS) { slot = deg; g_ndst[v*SLOTS + deg] = dd; ++deg; }
            if (slot >= 0) {
                g_eslot[e] = slot;
                if (ecnt < MAXE) g_vedge[v*MAXE + ecnt++] = e | (slot << 16);
            }
        }
    }
    g_ndeg[v] = deg;
    g_ecnt[v] = ecnt;
    for (int b = 0; b < B_; ++b)
        for (int k = 0; k < SLOTS; ++k)
            g_adjw[(b*V_ + v)*SLOTS + k] = 0.f;
}

__global__ void k1b_adjw(const int* __restrict__ ei, const float* __restrict__ ew) {
    const int i = blockIdx.x * blockDim.x + threadIdx.x;
    if (i >= BE_) return;
    const int e = i & (E_ - 1);
    const int b = i >> 10;
    const int v = ei[i];
    const int slot = g_eslot[e];
    atomicAdd(&g_adjw[(b*V_ + v)*SLOTS + slot], ew[i]);
}

// ---------------- K2: fused per-(b,l) attention, HMMA + register B ----------------
__global__ void __launch_bounds__(512, 1) k2_main(
    const float* __restrict__ hs, const float* __restrict__ attn_skip,
    float* __restrict__ ew_out) {
    extern __shared__ __align__(16) unsigned char sm[];
    const uint32_t sb = smem_u32(sm);
    const int tid = threadIdx.x;
    const int lane = tid & 31, warp = tid >> 5;
    const int b = blockIdx.x >> 10;
    const int l = blockIdx.x & 1023;

    int*   sDst  = (int*)(sm + MS_DST);
    float* sAdj  = (float*)(sm + MS_ADJ);
    int*   sVed  = (int*)(sm + MS_VED);
    int*   sDeg  = (int*)(sm + MS_DEG);
    int*   sEcnt = (int*)(sm + MS_ECNT);
    float* sP    = (float*)(sm + MS_P);
    float* sR    = (float*)(sm + MS_R);
    float* sPp   = (float*)(sm + MS_PP);
    float* sRp   = (float*)(sm + MS_RP);
    float* sMx   = (float*)(sm + MS_MX);
    float* sInv  = (float*)(sm + MS_INV);
    float* sS    = (float*)(sm + SM_S);   // [64][68]

    // metadata
    if (tid < 64) { sDeg[tid] = g_ndeg[tid]; sEcnt[tid] = g_ecnt[tid]; }
    for (int i = tid; i < 64*SLOTS; i += 512) {
        sDst[i] = g_ndst[i];
        sAdj[i] = g_adjw[b*64*SLOTS + i];
    }
    for (int i = tid; i < 64*MAXE; i += 512) sVed[i] = g_vedge[i];

    // H load + bf16 split + bias partials
    {
        const int v = tid >> 3, part = tid & 7;
        const float4* hrow = (const float4*)(hs
            + (((size_t)(b*64 + v))*1024 + l)*256) + part*8;
        const float4* u4 = (const float4*)g_u + part*8;
        const float4* t4 = (const float4*)g_t + part*8;
        float pp = 0.f, rr = 0.f;
#pragma unroll
        for (int i = 0; i < 8; ++i) {
            float4 f = hrow[i];
            float4 uu = u4[i], tt = t4[i];
            pp += f.x*uu.x + f.y*uu.y + f.z*uu.z + f.w*uu.w;
            rr += f.x*tt.x + f.y*tt.y + f.z*tt.z + f.w*tt.w;
            __nv_bfloat16 h0 = __float2bfloat16(f.x), h1 = __float2bfloat16(f.y);
            __nv_bfloat16 h2 = __float2bfloat16(f.z), h3 = __float2bfloat16(f.w);
            uint32_t hi01, hi23, lo01, lo23;
            { __nv_bfloat162 t2 = make_bfloat162(h0, h1); hi01 = *(uint32_t*)&t2; }
            { __nv_bfloat162 t2 = make_bfloat162(h2, h3); hi23 = *(uint32_t*)&t2; }
            lo01 = pack_bf2(f.x - __bfloat162float(h0), f.y - __bfloat162float(h1));
            lo23 = pack_bf2(f.z - __bfloat162float(h2), f.w - __bfloat162float(h3));
            const uint32_t off = (uint32_t)v*ASTR + (uint32_t)(part*32 + i*4)*2;
            *(uint2*)(sm + SM_AHI + off) = make_uint2(hi01, hi23);
            *(uint2*)(sm + SM_ALO + off) = make_uint2(lo01, lo23);
        }
        sPp[tid] = pp; sRp[tid] = rr;
    }
    __syncthreads();

    // bias reduction
    if (tid < 64) {
        float p = 0.f, r = 0.f;
#pragma unroll
        for (int i = 0; i < 8; ++i) { p += sPp[tid*8 + i]; r += sRp[tid*8 + i]; }
        sP[tid] = p; sR[tid] = r;
    }

    // ---- GEMM1: T(64x256) = Hsplit @ Mt, B fragments via direct LDG ----
    const int mg = warp >> 3;          // 0..1 (32 rows)
    const int ng = warp & 7;           // 0..7 (32 cols)
    const int arow = lane & 15;
    const int akoff = (lane >> 4) * 8;
    const int bjoff = ((lane >> 4) << 3) + (lane & 7);
    const int bdk = ((lane >> 3) & 1) * 8;

    const uint4* BH = (const uint4*)g_BfH;
    const uint4* BL = (const uint4*)g_BfL;
    // uint4 index for (grp, s): ((ng*2+grp)*16 + s)*32 + lane
    const int bbase0 = ((ng*2 + 0)*16)*32 + lane;
    const int bbase1 = ((ng*2 + 1)*16)*32 + lane;

    float acc[2][4][4];
#pragma unroll
    for (int mt = 0; mt < 2; ++mt)
#pragma unroll
        for (int n8 = 0; n8 < 4; ++n8)
#pragma unroll
            for (int i = 0; i < 4; ++i) acc[mt][n8][i] = 0.f;

    uint4 cH[2], cL[2];
    cH[0] = BH[bbase0]; cH[1] = BH[bbase1];
    cL[0] = BL[bbase0]; cL[1] = BL[bbase1];

    for (int s = 0; s < 16; ++s) {
        uint4 nH0, nH1, nL0, nL1;
        if (s < 15) {
            nH0 = BH[bbase0 + (s+1)*32]; nH1 = BH[bbase1 + (s+1)*32];
            nL0 = BL[bbase0 + (s+1)*32]; nL1 = BL[bbase1 + (s+1)*32];
        }
        uint32_t aHi[2][4], aLo[2][4];
#pragma unroll
        for (int mt = 0; mt < 2; ++mt) {
            const uint32_t ao = (uint32_t)(mg*32 + mt*16 + arow)*ASTR + (uint32_t)(s*16 + akoff)*2;
            ldsm4(aHi[mt], sb + SM_AHI + ao);
            ldsm4(aLo[mt], sb + SM_ALO + ao);
        }
#pragma unroll
        for (int mt = 0; mt < 2; ++mt)
#pragma unroll
            for (int grp = 0; grp < 2; ++grp) {
                mma16816(acc[mt][grp*2+0], aHi[mt], cH[grp].x, cH[grp].y);
                mma16816(acc[mt][grp*2+0], aHi[mt], cL[grp].x, cL[grp].y);
                mma16816(acc[mt][grp*2+0], aLo[mt], cH[grp].x, cH[grp].y);
                mma16816(acc[mt][grp*2+1], aHi[mt], cH[grp].z, cH[grp].w);
                mma16816(acc[mt][grp*2+1], aHi[mt], cL[grp].z, cL[grp].w);
                mma16816(acc[mt][grp*2+1], aLo[mt], cH[grp].z, cH[grp].w);
            }
        if (s < 15) {
            cH[0] = nH0; cH[1] = nH1; cL[0] = nL0; cL[1] = nL1;
        }
    }

    // ---- T -> bf16 split into sThi/sTlo ----
    {
        const int g = lane >> 2, t2 = lane & 3;
#pragma unroll
        for (int mt = 0; mt < 2; ++mt)
#pragma unroll
            for (int n8 = 0; n8 < 4; ++n8) {
                const int col = ng*32 + n8*8 + t2*2;
                const int r0 = mg*32 + mt*16 + g;
#pragma unroll
                for (int half = 0; half < 2; ++half) {
                    const float c0 = acc[mt][n8][half*2], c1 = acc[mt][n8][half*2 + 1];
                    const int row = r0 + half*8;
                    __nv_bfloat16 h0 = __float2bfloat16(c0), h1 = __float2bfloat16(c1);
                    __nv_bfloat162 hp = make_bfloat162(h0, h1);
                    const uint32_t hv = *(uint32_t*)&hp;
                    const uint32_t lv = pack_bf2(c0 - __bfloat162float(h0), c1 - __bfloat162float(h1));
                    const uint32_t off = (uint32_t)row*ASTR + (uint32_t)col*2;
                    *(uint32_t*)(sm + SM_THI + off) = hv;
                    *(uint32_t*)(sm + SM_TLO + off) = lv;
                }
            }
    }
    __syncthreads();

    // ---- GEMM2: S(64x64) = Tsplit @ Hsplit^T ----
    {
        const int mg2 = warp >> 2;      // 0..3 (16 rows)
        const int ng2 = warp & 3;       // 0..3 (16 cols)
        float acc2[2][4];
#pragma unroll
        for (int q = 0; q < 2; ++q)
#pragma unroll
            for (int i = 0; i < 4; ++i) acc2[q][i] = 0.f;

        for (int s = 0; s < 16; ++s) {
            uint32_t aHi[4], aLo[4], bHi[4], bLo[4];
            const uint32_t ao = (uint32_t)(mg2*16 + arow)*ASTR + (uint32_t)(s*16 + akoff)*2;
            ldsm4(aHi, sb + SM_THI + ao);
            ldsm4(aLo, sb + SM_TLO + ao);
            const uint32_t bo = (uint32_t)(ng2*16 + bjoff)*ASTR + (uint32_t)(s*16 + bdk)*2;
            ldsm4(bHi, sb + SM_AHI + bo);
            ldsm4(bLo, sb + SM_ALO + bo);
#pragma unroll
            for (int q = 0; q < 2; ++q) {
                mma16816(acc2[q], aHi, bHi[2*q], bHi[2*q+1]);
                mma16816(acc2[q], aHi, bLo[2*q], bLo[2*q+1]);
                mma16816(acc2[q], aLo, bHi[2*q], bHi[2*q+1]);
            }
        }
        const int g = lane >> 2, t2 = lane & 3;
#pragma unroll
        for (int q = 0; q < 2; ++q) {
            const int col = ng2*16 + q*8 + t2*2;
            *(float2*)&sS[(mg2*16 + g)*68 + col]     = make_float2(acc2[q][0], acc2[q][1]);
            *(float2*)&sS[(mg2*16 + g + 8)*68 + col] = make_float2(acc2[q][2], acc2[q][3]);
        }
    }
    __syncthreads();

    // ---- softmax step 1: per-v max & inv-sum ----
    if (tid < 64) {
        const int v = tid, deg = sDeg[v];
        const float pv = sP[v], cC = g_c;
        float mx = -1e30f;
        float sc[SLOTS];
        for (int k = 0; k < deg; ++k) {
            const int w = sDst[v*SLOTS + k];
            const float s = (sS[v*68 + w] + pv + sR[w] + cC) * 0.0625f;
            sc[k] = s;
            mx = fmaxf(mx, s);
        }
        float sum = 0.f;
        for (int k = 0; k < deg; ++k) sum += __expf(sc[k] - mx);
        sMx[v] = mx;
        sInv[v] = 1.f / sum;
    }
    __syncthreads();

    // ---- step 2: parallel per-edge output (512 threads, 2 edges each) ----
    {
        const int v = tid >> 3;
        const int j0 = (tid & 7) * 2;
        const int ecnt = sEcnt[v];
        const float pv = sP[v], cC = g_c;
        const float mx = sMx[v], inv = sInv[v];
        const float ask = *attn_skip, osk = 1.f - ask;
#pragma unroll
        for (int jj = 0; jj < 2; ++jj) {
            const int j = j0 + jj;
            if (j < ecnt) {
                const int w = sVed[v*MAXE + j];
                const int e = w & 0xFFFF, slot = w >> 16;
                const int dd = sDst[v*SLOTS + slot];
                const float s = (sS[v*68 + dd] + pv + sR[dd] + cC) * 0.0625f;
                const float gval = ask * sAdj[v*SLOTS + slot] + osk * (__expf(s - mx) * inv);
                ew_out[((size_t)(b*E_ + e))*L_ + l] = gval;
            }
        }
    }
}

// ---------------- K3: ei broadcast output ----------------
__global__ void k3_ei(const int* __restrict__ ei, float* __restrict__ out) {
    const size_t i = (size_t)blockIdx.x * blockDim.x + threadIdx.x;
    const size_t n = (size_t)2 * BE_ * L_;
    if (i < n) out[i] = (float)ei[i >> 10];
}

// ---------------- launch ----------------
extern "C" void kernel_launch(void* const* d_in, const int* in_sizes, int n_in,
                              void* d_out, int out_size) {
    const float* hs  = (const float*)d_in[0];
    const int*   ei  = (const int*)d_in[1];
    const float* ew  = (const float*)d_in[2];
    const float* Wq  = (const float*)d_in[3];
    const float* bq  = (const float*)d_in[4];
    const float* Wk  = (const float*)d_in[5];
    const float* bk  = (const float*)d_in[6];
    const float* ask = (const float*)d_in[7];

    float* out = (float*)d_out;
    const int EW_ELEMS = BE_ * L_;
    const int EI_ELEMS = 2 * BE_ * L_;
    float* ew_out = out;
    bool write_ei = false;
    if (out_size >= EI_ELEMS + EW_ELEMS) {
        write_ei = true;
        ew_out = out + EI_ELEMS;
    }

    cudaFuncSetAttribute(k2_main, cudaFuncAttributeMaxDynamicSharedMemorySize, SMEM_BYTES);

    k0_prep<<<D_, D_>>>(Wq, bq, Wk, bk);
    k1_build<<<1, V_>>>(ei);
    k1b_adjw<<<(BE_ + 255)/256, 256>>>(ei, ew);
    k2_main<<<B_*L_, 512, SMEM_BYTES>>>(hs, ask, ew_out);
    if (write_ei) k3_ei<<<(EI_ELEMS + 255)/256, 256>>>(ei, out);
}